// round 3
// baseline (speedup 1.0000x reference)
#include <cuda_runtime.h>

#define NN 50000
#define DD 128
#define LN_EPS 1e-5f
#define ROWS 32            // rows per GEMM block
#define KCHUNK 32          // K-tile for W staging

// ---- scratch (device globals; zero-initialized at module load) ----
__device__ float g_deg_out[NN];
__device__ float g_deg_in[NN];
__device__ float g_iso[NN];
__device__ float g_isi[NN];
__device__ float g_agg[NN * DD];
__device__ float g_h1[NN * DD];

// ---- zero degree arrays (g_agg is re-zeroed by gemm_ln_kernel each layer) ----
__global__ void zero_deg_kernel() {
    int i = blockIdx.x * blockDim.x + threadIdx.x;
    if (i < NN) { g_deg_out[i] = 0.f; g_deg_in[i] = 0.f; }
}

// ---- degree accumulation (indices are INT32: JAX default x64-disabled) ----
__global__ void degree_kernel(const int* __restrict__ src,
                              const int* __restrict__ dst, int E) {
    int t = blockIdx.x * blockDim.x + threadIdx.x;
    if (t >= E) return;
    atomicAdd(&g_deg_out[src[t]], 1.f);
    atomicAdd(&g_deg_in[dst[t]], 1.f);
}

// ---- inverse-sqrt norms ----
__global__ void norm_kernel() {
    int t = blockIdx.x * blockDim.x + threadIdx.x;
    if (t >= NN) return;
    g_iso[t] = rsqrtf(fmaxf(g_deg_out[t], 1.f));
    g_isi[t] = rsqrtf(fmaxf(g_deg_in[t], 1.f));
}

// ---- SpMM: one warp per edge. g_agg[dst] += x[src] * iso[src] ----
// x == nullptr -> read from g_h1 (layer 2).
__global__ void spmm_kernel(const float* __restrict__ x,
                            const int* __restrict__ src,
                            const int* __restrict__ dst, int E) {
    int gtid = blockIdx.x * blockDim.x + threadIdx.x;
    int e = gtid >> 5;
    int lane = gtid & 31;
    if (e >= E) return;
    const float* xx = (x != nullptr) ? x : (const float*)g_h1;
    int s = src[e];
    int d = dst[e];
    float sc = g_iso[s];
    float4 v = reinterpret_cast<const float4*>(xx)[s * 32 + lane];
    float* ap = g_agg + d * DD + lane * 4;
    atomicAdd(ap + 0, v.x * sc);   // result unused -> REDG
    atomicAdd(ap + 1, v.y * sc);
    atomicAdd(ap + 2, v.z * sc);
    atomicAdd(ap + 3, v.w * sc);
}

// ---- fused: y = ReLU(LN((g_agg * isi) @ W + b)); zeroes g_agg behind itself.
// block = 256 threads (8 warps), ROWS=32 rows/block.
// warp w owns rows w*4..w*4+3; lane owns cols lane*4..lane*4+3 (float4).
// W staged in K-chunks of 32 rows (16 KB) -> 32 KB static smem total.
// outg == nullptr -> write to g_h1 (layer 1).
__global__ void gemm_ln_kernel(const float* __restrict__ Wg,
                               const float* __restrict__ bg,
                               const float* __restrict__ gg,
                               const float* __restrict__ beg,
                               float* __restrict__ outg) {
    __shared__ float Ws[KCHUNK * DD];   // 16 KB
    __shared__ float xs[ROWS * DD];     // 16 KB
    int t = threadIdx.x;
    int warp = t >> 5, lane = t & 31;
    int row0 = blockIdx.x * ROWS;

    float* out = (outg != nullptr) ? outg : (float*)g_h1;

    float4 bv  = reinterpret_cast<const float4*>(bg)[lane];
    float4 gv  = reinterpret_cast<const float4*>(gg)[lane];
    float4 bev = reinterpret_cast<const float4*>(beg)[lane];

    // load 32 rows of g_agg, scale by isi, zero the source behind us
    float4* xs4 = reinterpret_cast<float4*>(xs);
    float4* agg4 = reinterpret_cast<float4*>(g_agg);
    #pragma unroll
    for (int i = t; i < ROWS * 32; i += 256) {
        int r = i >> 5, c = i & 31;
        int grow = row0 + r;
        float4 v = make_float4(0.f, 0.f, 0.f, 0.f);
        if (grow < NN) {
            v = agg4[grow * 32 + c];
            float sc = g_isi[grow];
            v.x *= sc; v.y *= sc; v.z *= sc; v.w *= sc;
            agg4[grow * 32 + c] = make_float4(0.f, 0.f, 0.f, 0.f);
        }
        xs4[i] = v;
    }

    int rb = warp * 4;
    float4 acc0 = bv, acc1 = bv, acc2 = bv, acc3 = bv;
    const float4* W4 = reinterpret_cast<const float4*>(Wg);
    float4* Ws4 = reinterpret_cast<float4*>(Ws);

    #pragma unroll
    for (int kc = 0; kc < DD / KCHUNK; kc++) {
        __syncthreads();
        // stage W rows [kc*32, kc*32+32) : 1024 float4, 256 threads x 4
        #pragma unroll
        for (int i = t; i < KCHUNK * 32; i += 256)
            Ws4[i] = W4[kc * KCHUNK * 32 + i];
        __syncthreads();

        #pragma unroll 8
        for (int k = 0; k < KCHUNK; k++) {
            float4 w = Ws4[k * 32 + lane];
            float x0 = xs[(rb + 0) * DD + kc * KCHUNK + k];
            float x1 = xs[(rb + 1) * DD + kc * KCHUNK + k];
            float x2 = xs[(rb + 2) * DD + kc * KCHUNK + k];
            float x3 = xs[(rb + 3) * DD + kc * KCHUNK + k];
            acc0.x += x0 * w.x; acc0.y += x0 * w.y; acc0.z += x0 * w.z; acc0.w += x0 * w.w;
            acc1.x += x1 * w.x; acc1.y += x1 * w.y; acc1.z += x1 * w.z; acc1.w += x1 * w.w;
            acc2.x += x2 * w.x; acc2.y += x2 * w.y; acc2.z += x2 * w.z; acc2.w += x2 * w.w;
            acc3.x += x3 * w.x; acc3.y += x3 * w.y; acc3.z += x3 * w.z; acc3.w += x3 * w.w;
        }
    }

    // LayerNorm + ReLU per row (each row lives in one warp)
    float4* out4 = reinterpret_cast<float4*>(out);
    float4 accs[4] = {acc0, acc1, acc2, acc3};
    #pragma unroll
    for (int r = 0; r < 4; r++) {
        float4 a = accs[r];
        float s  = a.x + a.y + a.z + a.w;
        float sq = a.x * a.x + a.y * a.y + a.z * a.z + a.w * a.w;
        #pragma unroll
        for (int off = 16; off > 0; off >>= 1) {
            s  += __shfl_xor_sync(0xFFFFFFFF, s,  off);
            sq += __shfl_xor_sync(0xFFFFFFFF, sq, off);
        }
        float mu  = s * (1.f / DD);
        float var = sq * (1.f / DD) - mu * mu;
        float rs  = rsqrtf(var + LN_EPS);
        float4 o;
        o.x = fmaxf((a.x - mu) * rs * gv.x + bev.x, 0.f);
        o.y = fmaxf((a.y - mu) * rs * gv.y + bev.y, 0.f);
        o.z = fmaxf((a.z - mu) * rs * gv.z + bev.z, 0.f);
        o.w = fmaxf((a.w - mu) * rs * gv.w + bev.w, 0.f);
        int grow = row0 + rb + r;
        if (grow < NN) out4[grow * 32 + lane] = o;
    }
}

extern "C" void kernel_launch(void* const* d_in, const int* in_sizes, int n_in,
                              void* d_out, int out_size) {
    const float* feat = (const float*)d_in[0];
    const int*   src  = (const int*)d_in[1];   // int32 (JAX x64 disabled)
    const int*   dst  = (const int*)d_in[2];
    const float* W1  = (const float*)d_in[3];
    const float* b1  = (const float*)d_in[4];
    const float* g1  = (const float*)d_in[5];
    const float* be1 = (const float*)d_in[6];
    const float* W2  = (const float*)d_in[7];
    const float* b2  = (const float*)d_in[8];
    const float* g2  = (const float*)d_in[9];
    const float* be2 = (const float*)d_in[10];
    float* out = (float*)d_out;
    int E = in_sizes[1];

    // degrees + norms (g_agg starts zero: zero-init at load, re-zeroed by gemm)
    zero_deg_kernel<<<(NN + 255) / 256, 256>>>();
    degree_kernel<<<(E + 255) / 256, 256>>>(src, dst, E);
    norm_kernel<<<(NN + 255) / 256, 256>>>();

    int spmm_blocks = (int)(((long long)E * 32 + 255) / 256);
    int gemm_blocks = (NN + ROWS - 1) / ROWS;

    // layer 1: agg <- A_norm @ feat ; h1 <- ReLU(LN(agg@W1+b1)) ; agg re-zeroed
    spmm_kernel<<<spmm_blocks, 256>>>(feat, src, dst, E);
    gemm_ln_kernel<<<gemm_blocks, 256>>>(W1, b1, g1, be1, nullptr);

    // layer 2: agg <- A_norm @ h1 ; out <- ReLU(LN(agg@W2+b2)) ; agg re-zeroed
    spmm_kernel<<<spmm_blocks, 256>>>(nullptr, src, dst, E);
    gemm_ln_kernel<<<gemm_blocks, 256>>>(W2, b2, g2, be2, out);
}

// round 4
// speedup vs baseline: 2.5470x; 2.5470x over previous
#include <cuda_runtime.h>

#define NN 50000
#define EE 800000
#define DD 128
#define LN_EPS 1e-5f
#define ROWS 32            // rows per GEMM block
#define KCHUNK 32          // K-tile for W staging
#define SCAN_T 1024

// ---- scratch (device globals) ----
__device__ int   g_cnt_in[NN];
__device__ int   g_cnt_out[NN];
__device__ int   g_cursor[NN];
__device__ int   g_rowptr[NN + 1];
__device__ int   g_srcs[EE];        // CSC: src ids grouped by dst
__device__ float g_iso[NN];
__device__ float g_isi[NN];
__device__ float g_agg[NN * DD];
__device__ float g_h1[NN * DD];

// ---- zero counters ----
__global__ void zero_kernel() {
    int i = blockIdx.x * blockDim.x + threadIdx.x;
    if (i < NN) { g_cnt_in[i] = 0; g_cnt_out[i] = 0; g_cursor[i] = 0; }
}

// ---- int degree histogram ----
__global__ void degree_kernel(const int* __restrict__ src,
                              const int* __restrict__ dst, int E) {
    int t = blockIdx.x * blockDim.x + threadIdx.x;
    if (t >= E) return;
    atomicAdd(&g_cnt_out[src[t]], 1);
    atomicAdd(&g_cnt_in[dst[t]], 1);
}

// ---- inverse-sqrt norms ----
__global__ void norm_kernel() {
    int t = blockIdx.x * blockDim.x + threadIdx.x;
    if (t >= NN) return;
    g_iso[t] = rsqrtf(fmaxf((float)g_cnt_out[t], 1.f));
    g_isi[t] = rsqrtf(fmaxf((float)g_cnt_in[t], 1.f));
}

// ---- single-block exclusive scan of g_cnt_in -> g_rowptr ----
__global__ void scan_kernel() {
    __shared__ int sums[SCAN_T];
    int t = threadIdx.x;
    const int per = (NN + SCAN_T - 1) / SCAN_T;   // 49
    int b = t * per;
    int e = (b + per < NN) ? b + per : NN;
    int s = 0;
    for (int i = b; i < e; i++) s += g_cnt_in[i];
    sums[t] = s;
    __syncthreads();
    // Hillis-Steele inclusive scan
    for (int off = 1; off < SCAN_T; off <<= 1) {
        int v = (t >= off) ? sums[t - off] : 0;
        __syncthreads();
        sums[t] += v;
        __syncthreads();
    }
    int run = (t == 0) ? 0 : sums[t - 1];
    for (int i = b; i < e; i++) { g_rowptr[i] = run; run += g_cnt_in[i]; }
    if (t == SCAN_T - 1) g_rowptr[NN] = run;
}

// ---- scatter edges into CSC buckets ----
__global__ void scatter_kernel(const int* __restrict__ src,
                               const int* __restrict__ dst, int E) {
    int t = blockIdx.x * blockDim.x + threadIdx.x;
    if (t >= E) return;
    int d = dst[t];
    int pos = g_rowptr[d] + atomicAdd(&g_cursor[d], 1);
    g_srcs[pos] = src[t];
}

// ---- gather SpMM: one warp per dst node.
// agg[d] = isi[d] * sum_{s in N_in(d)} x[s] * iso[s]
// x == nullptr -> read from g_h1 (layer 2).
__global__ void spmm_gather_kernel(const float* __restrict__ x) {
    int gtid = blockIdx.x * blockDim.x + threadIdx.x;
    int d = gtid >> 5;
    int lane = gtid & 31;
    if (d >= NN) return;
    const float4* x4 = reinterpret_cast<const float4*>(
        (x != nullptr) ? x : (const float*)g_h1);

    int beg = g_rowptr[d], end = g_rowptr[d + 1];
    float4 acc = make_float4(0.f, 0.f, 0.f, 0.f);
    int p = beg;
    for (; p + 4 <= end; p += 4) {
        int s0 = g_srcs[p + 0], s1 = g_srcs[p + 1];
        int s2 = g_srcs[p + 2], s3 = g_srcs[p + 3];
        float c0 = g_iso[s0], c1 = g_iso[s1];
        float c2 = g_iso[s2], c3 = g_iso[s3];
        float4 v0 = x4[s0 * 32 + lane];
        float4 v1 = x4[s1 * 32 + lane];
        float4 v2 = x4[s2 * 32 + lane];
        float4 v3 = x4[s3 * 32 + lane];
        acc.x += v0.x * c0; acc.y += v0.y * c0; acc.z += v0.z * c0; acc.w += v0.w * c0;
        acc.x += v1.x * c1; acc.y += v1.y * c1; acc.z += v1.z * c1; acc.w += v1.w * c1;
        acc.x += v2.x * c2; acc.y += v2.y * c2; acc.z += v2.z * c2; acc.w += v2.w * c2;
        acc.x += v3.x * c3; acc.y += v3.y * c3; acc.z += v3.z * c3; acc.w += v3.w * c3;
    }
    for (; p < end; p++) {
        int s = g_srcs[p];
        float c = g_iso[s];
        float4 v = x4[s * 32 + lane];
        acc.x += v.x * c; acc.y += v.y * c; acc.z += v.z * c; acc.w += v.w * c;
    }
    float si = g_isi[d];
    acc.x *= si; acc.y *= si; acc.z *= si; acc.w *= si;
    reinterpret_cast<float4*>(g_agg)[d * 32 + lane] = acc;
}

// ---- fused: y = ReLU(LN(g_agg @ W + b))  (isi already applied in gather)
// block = 256 threads (8 warps), ROWS=32 rows/block.
// outg == nullptr -> write to g_h1 (layer 1).
__global__ void gemm_ln_kernel(const float* __restrict__ Wg,
                               const float* __restrict__ bg,
                               const float* __restrict__ gg,
                               const float* __restrict__ beg,
                               float* __restrict__ outg) {
    __shared__ float Ws[KCHUNK * DD];   // 16 KB
    __shared__ float xs[ROWS * DD];     // 16 KB
    int t = threadIdx.x;
    int warp = t >> 5, lane = t & 31;
    int row0 = blockIdx.x * ROWS;

    float* out = (outg != nullptr) ? outg : (float*)g_h1;

    float4 bv  = reinterpret_cast<const float4*>(bg)[lane];
    float4 gv  = reinterpret_cast<const float4*>(gg)[lane];
    float4 bev = reinterpret_cast<const float4*>(beg)[lane];

    // load 32 rows of g_agg into shared
    float4* xs4 = reinterpret_cast<float4*>(xs);
    const float4* agg4 = reinterpret_cast<const float4*>(g_agg);
    #pragma unroll
    for (int i = t; i < ROWS * 32; i += 256) {
        int r = i >> 5, c = i & 31;
        int grow = row0 + r;
        xs4[i] = (grow < NN) ? agg4[grow * 32 + c]
                             : make_float4(0.f, 0.f, 0.f, 0.f);
    }

    int rb = warp * 4;
    float4 acc0 = bv, acc1 = bv, acc2 = bv, acc3 = bv;
    const float4* W4 = reinterpret_cast<const float4*>(Wg);
    float4* Ws4 = reinterpret_cast<float4*>(Ws);

    #pragma unroll
    for (int kc = 0; kc < DD / KCHUNK; kc++) {
        __syncthreads();
        #pragma unroll
        for (int i = t; i < KCHUNK * 32; i += 256)
            Ws4[i] = W4[kc * KCHUNK * 32 + i];
        __syncthreads();

        #pragma unroll 8
        for (int k = 0; k < KCHUNK; k++) {
            float4 w = Ws4[k * 32 + lane];
            float x0 = xs[(rb + 0) * DD + kc * KCHUNK + k];
            float x1 = xs[(rb + 1) * DD + kc * KCHUNK + k];
            float x2 = xs[(rb + 2) * DD + kc * KCHUNK + k];
            float x3 = xs[(rb + 3) * DD + kc * KCHUNK + k];
            acc0.x += x0 * w.x; acc0.y += x0 * w.y; acc0.z += x0 * w.z; acc0.w += x0 * w.w;
            acc1.x += x1 * w.x; acc1.y += x1 * w.y; acc1.z += x1 * w.z; acc1.w += x1 * w.w;
            acc2.x += x2 * w.x; acc2.y += x2 * w.y; acc2.z += x2 * w.z; acc2.w += x2 * w.w;
            acc3.x += x3 * w.x; acc3.y += x3 * w.y; acc3.z += x3 * w.z; acc3.w += x3 * w.w;
        }
    }

    // LayerNorm + ReLU per row
    float4* out4 = reinterpret_cast<float4*>(out);
    float4 accs[4] = {acc0, acc1, acc2, acc3};
    #pragma unroll
    for (int r = 0; r < 4; r++) {
        float4 a = accs[r];
        float s  = a.x + a.y + a.z + a.w;
        float sq = a.x * a.x + a.y * a.y + a.z * a.z + a.w * a.w;
        #pragma unroll
        for (int off = 16; off > 0; off >>= 1) {
            s  += __shfl_xor_sync(0xFFFFFFFF, s,  off);
            sq += __shfl_xor_sync(0xFFFFFFFF, sq, off);
        }
        float mu  = s * (1.f / DD);
        float var = sq * (1.f / DD) - mu * mu;
        float rs  = rsqrtf(var + LN_EPS);
        float4 o;
        o.x = fmaxf((a.x - mu) * rs * gv.x + bev.x, 0.f);
        o.y = fmaxf((a.y - mu) * rs * gv.y + bev.y, 0.f);
        o.z = fmaxf((a.z - mu) * rs * gv.z + bev.z, 0.f);
        o.w = fmaxf((a.w - mu) * rs * gv.w + bev.w, 0.f);
        int grow = row0 + rb + r;
        if (grow < NN) out4[grow * 32 + lane] = o;
    }
}

extern "C" void kernel_launch(void* const* d_in, const int* in_sizes, int n_in,
                              void* d_out, int out_size) {
    const float* feat = (const float*)d_in[0];
    const int*   src  = (const int*)d_in[1];   // int32 (JAX x64 disabled)
    const int*   dst  = (const int*)d_in[2];
    const float* W1  = (const float*)d_in[3];
    const float* b1  = (const float*)d_in[4];
    const float* g1  = (const float*)d_in[5];
    const float* be1 = (const float*)d_in[6];
    const float* W2  = (const float*)d_in[7];
    const float* b2  = (const float*)d_in[8];
    const float* g2  = (const float*)d_in[9];
    const float* be2 = (const float*)d_in[10];
    float* out = (float*)d_out;
    int E = in_sizes[1];
    if (E > EE) E = EE;

    // graph build: histogram -> norms + scan -> scatter
    zero_kernel<<<(NN + 255) / 256, 256>>>();
    degree_kernel<<<(E + 255) / 256, 256>>>(src, dst, E);
    norm_kernel<<<(NN + 255) / 256, 256>>>();
    scan_kernel<<<1, SCAN_T>>>();
    scatter_kernel<<<(E + 255) / 256, 256>>>(src, dst, E);

    int gather_blocks = (NN * 32 + 255) / 256;
    int gemm_blocks = (NN + ROWS - 1) / ROWS;

    // layer 1
    spmm_gather_kernel<<<gather_blocks, 256>>>(feat);
    gemm_ln_kernel<<<gemm_blocks, 256>>>(W1, b1, g1, be1, nullptr);

    // layer 2
    spmm_gather_kernel<<<gather_blocks, 256>>>(nullptr);
    gemm_ln_kernel<<<gemm_blocks, 256>>>(W2, b2, g2, be2, out);
}

// round 5
// speedup vs baseline: 3.0972x; 1.2160x over previous
#include <cuda_runtime.h>

#define NN 50000
#define EE 800000
#define DD 128
#define LN_EPS 1e-5f
#define ROWS 32            // rows per GEMM block
#define KCHUNK 32          // K-tile for W staging
#define SCAN_B ((NN + 255) / 256)   // 196 blocks for block-scan

// ---- scratch (device globals) ----
__device__ int   g_cnt_in[NN];
__device__ int   g_cnt_out[NN];
__device__ int   g_cursor[NN];
__device__ int   g_rowptr[NN + 1];
__device__ int   g_part[SCAN_B];
__device__ int   g_partscan[SCAN_B];
__device__ int   g_srcs[EE];        // CSC: src ids grouped by dst
__device__ float g_iso[NN];
__device__ float g_isi[NN];
__device__ float g_agg[NN * DD];
__device__ float g_h1[NN * DD];

// ---- zero counters ----
__global__ void zero_kernel() {
    int i = blockIdx.x * blockDim.x + threadIdx.x;
    if (i < NN) { g_cnt_in[i] = 0; g_cnt_out[i] = 0; }
}

// ---- int degree histogram ----
__global__ void degree_kernel(const int* __restrict__ src,
                              const int* __restrict__ dst, int E) {
    int t = blockIdx.x * blockDim.x + threadIdx.x;
    if (t >= E) return;
    atomicAdd(&g_cnt_out[src[t]], 1);
    atomicAdd(&g_cnt_in[dst[t]], 1);
}

// ---- scan phase 1: per-block exclusive scan of cnt_in (+ fused norms) ----
__global__ void blockscan_kernel() {
    __shared__ int warp_sums[8];
    int tid = threadIdx.x;
    int idx = blockIdx.x * 256 + tid;
    int lane = tid & 31, warp = tid >> 5;

    int v = (idx < NN) ? g_cnt_in[idx] : 0;
    if (idx < NN) {
        g_iso[idx] = rsqrtf(fmaxf((float)g_cnt_out[idx], 1.f));
        g_isi[idx] = rsqrtf(fmaxf((float)v, 1.f));
    }

    int incl = v;
    #pragma unroll
    for (int off = 1; off < 32; off <<= 1) {
        int n = __shfl_up_sync(0xFFFFFFFF, incl, off);
        if (lane >= off) incl += n;
    }
    if (lane == 31) warp_sums[warp] = incl;
    __syncthreads();
    if (warp == 0 && lane < 8) {
        int ws = warp_sums[lane];
        #pragma unroll
        for (int off = 1; off < 8; off <<= 1) {
            int n = __shfl_up_sync(0x000000FF, ws, off);
            if (lane >= off) ws += n;
        }
        warp_sums[lane] = ws;
    }
    __syncthreads();
    int excl = incl - v + (warp > 0 ? warp_sums[warp - 1] : 0);
    if (idx < NN) g_rowptr[idx] = excl;          // block-local exclusive
    if (tid == 0) g_part[blockIdx.x] = warp_sums[7];
}

// ---- scan phase 2: scan the 196 block partials (single small block) ----
__global__ void partscan_kernel() {
    __shared__ int warp_sums[8];
    int tid = threadIdx.x;
    int lane = tid & 31, warp = tid >> 5;
    int v = (tid < SCAN_B) ? g_part[tid] : 0;
    int incl = v;
    #pragma unroll
    for (int off = 1; off < 32; off <<= 1) {
        int n = __shfl_up_sync(0xFFFFFFFF, incl, off);
        if (lane >= off) incl += n;
    }
    if (lane == 31) warp_sums[warp] = incl;
    __syncthreads();
    if (warp == 0 && lane < 8) {
        int ws = warp_sums[lane];
        #pragma unroll
        for (int off = 1; off < 8; off <<= 1) {
            int n = __shfl_up_sync(0x000000FF, ws, off);
            if (lane >= off) ws += n;
        }
        warp_sums[lane] = ws;
    }
    __syncthreads();
    int excl = incl - v + (warp > 0 ? warp_sums[warp - 1] : 0);
    if (tid < SCAN_B) g_partscan[tid] = excl;
}

// ---- scan phase 3: add block offsets; init cursor = rowptr ----
__global__ void addoff_kernel(int E) {
    int idx = blockIdx.x * 256 + threadIdx.x;
    if (idx < NN) {
        int r = g_rowptr[idx] + g_partscan[blockIdx.x];
        g_rowptr[idx] = r;
        g_cursor[idx] = r;
    }
    if (idx == 0) g_rowptr[NN] = E;
}

// ---- scatter edges into CSC buckets (cursor pre-seeded with rowptr) ----
__global__ void scatter_kernel(const int* __restrict__ src,
                               const int* __restrict__ dst, int E) {
    int t = blockIdx.x * blockDim.x + threadIdx.x;
    if (t >= E) return;
    int pos = atomicAdd(&g_cursor[dst[t]], 1);
    g_srcs[pos] = src[t];
}

// ---- gather SpMM: one warp per dst node.
// agg[d] = isi[d] * sum_{s in N_in(d)} x[s] * iso[s]
// x == nullptr -> read from g_h1 (layer 2).
__global__ void spmm_gather_kernel(const float* __restrict__ x) {
    int gtid = blockIdx.x * blockDim.x + threadIdx.x;
    int d = gtid >> 5;
    int lane = gtid & 31;
    if (d >= NN) return;
    const float4* x4 = reinterpret_cast<const float4*>(
        (x != nullptr) ? x : (const float*)g_h1);

    int beg = g_rowptr[d], end = g_rowptr[d + 1];
    float4 acc = make_float4(0.f, 0.f, 0.f, 0.f);
    int p = beg;
    for (; p + 4 <= end; p += 4) {
        int s0 = g_srcs[p + 0], s1 = g_srcs[p + 1];
        int s2 = g_srcs[p + 2], s3 = g_srcs[p + 3];
        float c0 = g_iso[s0], c1 = g_iso[s1];
        float c2 = g_iso[s2], c3 = g_iso[s3];
        float4 v0 = x4[s0 * 32 + lane];
        float4 v1 = x4[s1 * 32 + lane];
        float4 v2 = x4[s2 * 32 + lane];
        float4 v3 = x4[s3 * 32 + lane];
        acc.x += v0.x * c0; acc.y += v0.y * c0; acc.z += v0.z * c0; acc.w += v0.w * c0;
        acc.x += v1.x * c1; acc.y += v1.y * c1; acc.z += v1.z * c1; acc.w += v1.w * c1;
        acc.x += v2.x * c2; acc.y += v2.y * c2; acc.z += v2.z * c2; acc.w += v2.w * c2;
        acc.x += v3.x * c3; acc.y += v3.y * c3; acc.z += v3.z * c3; acc.w += v3.w * c3;
    }
    for (; p < end; p++) {
        int s = g_srcs[p];
        float c = g_iso[s];
        float4 v = x4[s * 32 + lane];
        acc.x += v.x * c; acc.y += v.y * c; acc.z += v.z * c; acc.w += v.w * c;
    }
    float si = g_isi[d];
    acc.x *= si; acc.y *= si; acc.z *= si; acc.w *= si;
    reinterpret_cast<float4*>(g_agg)[d * 32 + lane] = acc;
}

// ---- fused: y = ReLU(LN(g_agg @ W + b))  (isi already applied in gather)
// outg == nullptr -> write to g_h1 (layer 1).
__global__ void gemm_ln_kernel(const float* __restrict__ Wg,
                               const float* __restrict__ bg,
                               const float* __restrict__ gg,
                               const float* __restrict__ beg,
                               float* __restrict__ outg) {
    __shared__ float Ws[KCHUNK * DD];   // 16 KB
    __shared__ float xs[ROWS * DD];     // 16 KB
    int t = threadIdx.x;
    int warp = t >> 5, lane = t & 31;
    int row0 = blockIdx.x * ROWS;

    float* out = (outg != nullptr) ? outg : (float*)g_h1;

    float4 bv  = reinterpret_cast<const float4*>(bg)[lane];
    float4 gv  = reinterpret_cast<const float4*>(gg)[lane];
    float4 bev = reinterpret_cast<const float4*>(beg)[lane];

    // load 32 rows of g_agg into shared
    float4* xs4 = reinterpret_cast<float4*>(xs);
    const float4* agg4 = reinterpret_cast<const float4*>(g_agg);
    #pragma unroll
    for (int i = t; i < ROWS * 32; i += 256) {
        int r = i >> 5, c = i & 31;
        int grow = row0 + r;
        xs4[i] = (grow < NN) ? agg4[grow * 32 + c]
                             : make_float4(0.f, 0.f, 0.f, 0.f);
    }

    int rb = warp * 4;
    float4 acc0 = bv, acc1 = bv, acc2 = bv, acc3 = bv;
    const float4* W4 = reinterpret_cast<const float4*>(Wg);
    float4* Ws4 = reinterpret_cast<float4*>(Ws);

    #pragma unroll
    for (int kc = 0; kc < DD / KCHUNK; kc++) {
        __syncthreads();
        #pragma unroll
        for (int i = t; i < KCHUNK * 32; i += 256)
            Ws4[i] = W4[kc * KCHUNK * 32 + i];
        __syncthreads();

        #pragma unroll 8
        for (int k = 0; k < KCHUNK; k++) {
            float4 w = Ws4[k * 32 + lane];
            float x0 = xs[(rb + 0) * DD + kc * KCHUNK + k];
            float x1 = xs[(rb + 1) * DD + kc * KCHUNK + k];
            float x2 = xs[(rb + 2) * DD + kc * KCHUNK + k];
            float x3 = xs[(rb + 3) * DD + kc * KCHUNK + k];
            acc0.x += x0 * w.x; acc0.y += x0 * w.y; acc0.z += x0 * w.z; acc0.w += x0 * w.w;
            acc1.x += x1 * w.x; acc1.y += x1 * w.y; acc1.z += x1 * w.z; acc1.w += x1 * w.w;
            acc2.x += x2 * w.x; acc2.y += x2 * w.y; acc2.z += x2 * w.z; acc2.w += x2 * w.w;
            acc3.x += x3 * w.x; acc3.y += x3 * w.y; acc3.z += x3 * w.z; acc3.w += x3 * w.w;
        }
    }

    // LayerNorm + ReLU per row
    float4* out4 = reinterpret_cast<float4*>(out);
    float4 accs[4] = {acc0, acc1, acc2, acc3};
    #pragma unroll
    for (int r = 0; r < 4; r++) {
        float4 a = accs[r];
        float s  = a.x + a.y + a.z + a.w;
        float sq = a.x * a.x + a.y * a.y + a.z * a.z + a.w * a.w;
        #pragma unroll
        for (int off = 16; off > 0; off >>= 1) {
            s  += __shfl_xor_sync(0xFFFFFFFF, s,  off);
            sq += __shfl_xor_sync(0xFFFFFFFF, sq, off);
        }
        float mu  = s * (1.f / DD);
        float var = sq * (1.f / DD) - mu * mu;
        float rs  = rsqrtf(var + LN_EPS);
        float4 o;
        o.x = fmaxf((a.x - mu) * rs * gv.x + bev.x, 0.f);
        o.y = fmaxf((a.y - mu) * rs * gv.y + bev.y, 0.f);
        o.z = fmaxf((a.z - mu) * rs * gv.z + bev.z, 0.f);
        o.w = fmaxf((a.w - mu) * rs * gv.w + bev.w, 0.f);
        int grow = row0 + rb + r;
        if (grow < NN) out4[grow * 32 + lane] = o;
    }
}

extern "C" void kernel_launch(void* const* d_in, const int* in_sizes, int n_in,
                              void* d_out, int out_size) {
    const float* feat = (const float*)d_in[0];
    const int*   src  = (const int*)d_in[1];   // int32 (JAX x64 disabled)
    const int*   dst  = (const int*)d_in[2];
    const float* W1  = (const float*)d_in[3];
    const float* b1  = (const float*)d_in[4];
    const float* g1  = (const float*)d_in[5];
    const float* be1 = (const float*)d_in[6];
    const float* W2  = (const float*)d_in[7];
    const float* b2  = (const float*)d_in[8];
    const float* g2  = (const float*)d_in[9];
    const float* be2 = (const float*)d_in[10];
    float* out = (float*)d_out;
    int E = in_sizes[1];
    if (E > EE) E = EE;

    // graph build: histogram -> (norms + 3-phase scan) -> scatter
    zero_kernel<<<SCAN_B, 256>>>();
    degree_kernel<<<(E + 255) / 256, 256>>>(src, dst, E);
    blockscan_kernel<<<SCAN_B, 256>>>();
    partscan_kernel<<<1, 256>>>();
    addoff_kernel<<<SCAN_B, 256>>>(E);
    scatter_kernel<<<(E + 255) / 256, 256>>>(src, dst, E);

    int gather_blocks = (NN * 32 + 255) / 256;
    int gemm_blocks = (NN + ROWS - 1) / ROWS;

    // layer 1
    spmm_gather_kernel<<<gather_blocks, 256>>>(feat);
    gemm_ln_kernel<<<gemm_blocks, 256>>>(W1, b1, g1, be1, nullptr);

    // layer 2
    spmm_gather_kernel<<<gather_blocks, 256>>>(nullptr);
    gemm_ln_kernel<<<gemm_blocks, 256>>>(W2, b2, g2, be2, out);
}